// round 15
// baseline (speedup 1.0000x reference)
#include <cuda_runtime.h>
#include <cuda_fp16.h>
#include <stdint.h>
#include <math.h>

#define BATCH 4
#define SEQ   2048
#define NDIM  768
#define HDIM  768
#define MTOT  (BATCH * SEQ)
#define WSZ   (HDIM * NDIM)

typedef __half hf;

// ------------------------- scratch (allocation-free) ------------------------
__device__ __align__(16) hf    g_xh[MTOT * NDIM];
__device__ __align__(16) hf    g_xl[MTOT * NDIM];
__device__ __align__(16) hf    g_wch[3 * WSZ];   // concat wq|wk|wv planes
__device__ __align__(16) hf    g_wcl[3 * WSZ];
__device__ __align__(16) hf    g_woh[WSZ];
__device__ __align__(16) hf    g_wol[WSZ];
__device__ __align__(16) hf    g_qh[MTOT * HDIM];
__device__ __align__(16) hf    g_ql[MTOT * HDIM];
__device__ __align__(16) hf    g_kh[MTOT * HDIM];
__device__ __align__(16) hf    g_kl[MTOT * HDIM];
__device__ __align__(16) hf    g_vth[(long long)BATCH * HDIM * SEQ];
__device__ __align__(16) float g_s [2LL * BATCH * SEQ * SEQ];   // QK^T split-K partial planes
__device__ __align__(16) hf    g_sh[(long long)BATCH * SEQ * SEQ];
__device__ __align__(16) hf    g_yh[MTOT * HDIM];
__device__ __align__(16) float g_py[2LL * MTOT * HDIM];   // PV split-K partials

// ------------------------------ helpers -------------------------------------
__device__ __forceinline__ void mma16816(float* d, const uint32_t* a, const uint32_t* b)
{
    asm volatile(
        "mma.sync.aligned.m16n8k16.row.col.f32.f16.f16.f32 "
        "{%0,%1,%2,%3},{%4,%5,%6,%7},{%8,%9},{%0,%1,%2,%3};\n"
        : "+f"(d[0]), "+f"(d[1]), "+f"(d[2]), "+f"(d[3])
        : "r"(a[0]), "r"(a[1]), "r"(a[2]), "r"(a[3]), "r"(b[0]), "r"(b[1]));
}

__device__ __forceinline__ void ldsm_x4(uint32_t* r, uint32_t addr)
{
    asm volatile("ldmatrix.sync.aligned.m8n8.x4.shared.b16 {%0,%1,%2,%3}, [%4];"
                 : "=r"(r[0]), "=r"(r[1]), "=r"(r[2]), "=r"(r[3]) : "r"(addr));
}

__device__ __forceinline__ void split1(float x, hf& h, hf& l)
{
    h = __float2half(x);
    l = __float2half(x - __half2float(h));
}

__device__ __forceinline__ void cpa16(uint32_t dst, const void* src)
{
    asm volatile("cp.async.cg.shared.global [%0], [%1], 16;\n" :: "r"(dst), "l"(src));
}
__device__ __forceinline__ void cpa_commit() { asm volatile("cp.async.commit_group;\n"); }
template <int N>
__device__ __forceinline__ void cpa_wait() { asm volatile("cp.async.wait_group %0;\n" :: "n"(N)); }

// smem geometry (uint32 words). Row = 16 data words (32 halves of k) + 4 pad.
#define RSTRIDE 20
#define PLANE_W (128 * RSTRIDE)
#define PLANE_B (PLANE_W * 4)
#define STAGE_B (4 * PLANE_B)                // 40960 B
#define SMEM_BYTES (2 * STAGE_B)             // 81920

// ---------------------------------------------------------------------------
// Split-fp16 tensor-core GEMM: C = A * B^T (+bias), split-K capable.
// EPI=0: fp32 Cf (adds bias0 if non-null).
// EPI=2: fused-QKV: seg0/1 -> split q/k planes; seg2 -> v written TRANSPOSED
//        (fp16) into C3h=[B,HDIM,SEQ], bias folded.
// Terms:  NT=1: hh.  NT=2: hh+hl.  NT=3: hh+hl+lh.
//         NT=23: QKV fused — q/k segs 3-term, v seg 1-term.
// ---------------------------------------------------------------------------
template <int EPI, int NT>
__global__ void __launch_bounds__(256, 2) hfs_gemm(
    const hf* __restrict__ Ah, const hf* __restrict__ Al,
    const hf* __restrict__ Bh, const hf* __restrict__ Bl,
    const float* __restrict__ bias0, const float* __restrict__ bias1,
    const float* __restrict__ bias2,
    float* __restrict__ Cf,
    hf* __restrict__ Ch, hf* __restrict__ Cl,
    hf* __restrict__ C2h, hf* __restrict__ C2l,
    hf* __restrict__ C3h, hf* __restrict__ C3l,
    int M, int N, int Kloop, int lda, int ldb, int ldc,
    int nsplit,
    long long sA, long long sB, long long sC,
    long long kOffA, long long kOffB, long long sSplit)
{
    extern __shared__ uint32_t smem[];

    const int bz = blockIdx.z;
    const int batch = bz / nsplit;
    const int split = bz - batch * nsplit;

    Ah += (long long)batch * sA + split * kOffA;
    Al += (long long)batch * sA + split * kOffA;
    Bh += (long long)batch * sB + split * kOffB;
    Bl += (long long)batch * sB + split * kOffB;
    if (EPI == 0) Cf += (long long)batch * sC + split * sSplit;

    const int tid  = threadIdx.x;
    const int lane = tid & 31;
    const int warp = tid >> 5;
    const int bm = blockIdx.y * 128;
    const int bn = blockIdx.x * 128;
    const int wm = (warp & 1) * 64;
    const int wn = (warp >> 1) * 32;
    const int r = lane >> 2;
    const int c = lane & 3;

    const int seg = (EPI == 2) ? (bn / 768) : 0;
    // term flags (CTA-uniform)
    const bool aLo = (NT == 3) || (NT == 23 && seg < 2);
    const bool bLo = (NT == 23) ? (seg < 2) : (NT >= 2);

    // ---- loader mapping: thread -> row=tid/2, two 16B chunks per plane ----
    const int ld_row = tid >> 1;
    const int ld_c0  = (tid & 1) * 2;
    const hf* pAh = Ah + (long long)(bm + ld_row) * lda + ld_c0 * 8;
    const hf* pAl = Al + (long long)(bm + ld_row) * lda + ld_c0 * 8;
    const hf* pBh = Bh + (long long)(bn + ld_row) * ldb + ld_c0 * 8;
    const hf* pBl = Bl + (long long)(bn + ld_row) * ldb + ld_c0 * 8;

    uint32_t smem_u32;
    asm("{ .reg .u64 t; cvta.to.shared.u64 t, %1; cvt.u32.u64 %0, t; }"
        : "=r"(smem_u32) : "l"(smem));
    const uint32_t dst_base = smem_u32 + (ld_row * RSTRIDE + 4 * ld_c0) * 4;

    auto load_stage = [&](int stage, int k0) {
        const uint32_t d = dst_base + stage * STAGE_B;
        cpa16(d,                pAh + k0);
        cpa16(d + 16,           pAh + k0 + 8);
        if (aLo) {
            cpa16(d + PLANE_B,      pAl + k0);
            cpa16(d + PLANE_B + 16, pAl + k0 + 8);
        }
        cpa16(d + 2 * PLANE_B,      pBh + k0);
        cpa16(d + 2 * PLANE_B + 16, pBh + k0 + 8);
        if (bLo) {
            cpa16(d + 3 * PLANE_B,      pBl + k0);
            cpa16(d + 3 * PLANE_B + 16, pBl + k0 + 8);
        }
    };

    const uint32_t aOff = (((wm + (lane & 15)) * RSTRIDE + ((lane >> 4) << 2)) << 2);
    const uint32_t bOff = (((wn + (lane & 7) + ((lane >> 4) << 3)) * RSTRIDE
                            + (((lane >> 3) & 1) << 2)) << 2);

    float acc[4][4][4];
    #pragma unroll
    for (int i = 0; i < 4; i++)
        #pragma unroll
        for (int j = 0; j < 4; j++)
            #pragma unroll
            for (int e = 0; e < 4; e++) acc[i][j][e] = 0.f;

    const int T = Kloop / 32;

    load_stage(0, 0);  cpa_commit();
    if (T > 1) load_stage(1, 32);
    cpa_commit();

    for (int t = 0; t < T; t++) {
        cpa_wait<1>();
        __syncthreads();

        const uint32_t stage_base = smem_u32 + (t & 1) * STAGE_B;
        const uint32_t aBaseH = stage_base + aOff;
        const uint32_t aBaseL = aBaseH + PLANE_B;
        const uint32_t bBaseH = stage_base + 2 * PLANE_B + bOff;
        const uint32_t bBaseL = bBaseH + PLANE_B;

        #pragma unroll
        for (int ks = 0; ks < 2; ks++) {
            const uint32_t kb = ks * 32;
            uint32_t aH[4][4], aL[4][4], bH[4][2], bL[4][2];
            #pragma unroll
            for (int mi = 0; mi < 4; mi++) {
                ldsm_x4(aH[mi], aBaseH + mi * (16 * RSTRIDE * 4) + kb);
                if (aLo)
                    ldsm_x4(aL[mi], aBaseL + mi * (16 * RSTRIDE * 4) + kb);
            }
            #pragma unroll
            for (int np = 0; np < 2; np++) {
                uint32_t th[4];
                ldsm_x4(th, bBaseH + np * (16 * RSTRIDE * 4) + kb);
                bH[2*np][0] = th[0]; bH[2*np][1] = th[1];
                bH[2*np+1][0] = th[2]; bH[2*np+1][1] = th[3];
                if (bLo) {
                    uint32_t tl[4];
                    ldsm_x4(tl, bBaseL + np * (16 * RSTRIDE * 4) + kb);
                    bL[2*np][0] = tl[0]; bL[2*np][1] = tl[1];
                    bL[2*np+1][0] = tl[2]; bL[2*np+1][1] = tl[3];
                }
            }
            #pragma unroll
            for (int mi = 0; mi < 4; mi++)
                #pragma unroll
                for (int ni = 0; ni < 4; ni++) {
                    mma16816(acc[mi][ni], aH[mi], bH[ni]);
                    if (bLo) mma16816(acc[mi][ni], aH[mi], bL[ni]);
                    if (aLo) mma16816(acc[mi][ni], aL[mi], bH[ni]);
                }
        }
        __syncthreads();

        if (t + 2 < T) load_stage(t & 1, (t + 2) * 32);
        cpa_commit();
    }

    // ---------------- epilogue ----------------
    const float* bias = bias0;
    hf* dh = Ch; hf* dl = Cl;
    int cb = bn;
    int stride = ldc;
    if (EPI == 2) {
        cb = bn - seg * 768;
        stride = 768;
        if (seg == 1) { bias = bias1; dh = C2h; dl = C2l; }
        else if (seg == 2) { bias = bias2; }
    }

    if (EPI == 2 && seg == 2) {
        // ---- v segment: bias + fp16, written TRANSPOSED into C3h[B,HDIM,SEQ]
        __syncthreads();   // all warps done with pipeline smem (LDSM complete)
        hf* st = reinterpret_cast<hf*>(smem);
        #pragma unroll
        for (int mi = 0; mi < 4; mi++)
            #pragma unroll
            for (int ni = 0; ni < 4; ni++) {
                const int rl = wm + mi * 16 + r;
                const int cl = wn + ni * 8 + 2 * c;
                const float b0 = bias[cb + cl], b1 = bias[cb + cl + 1];
                st[cl * 136 + rl]           = __float2half(acc[mi][ni][0] + b0);
                st[(cl + 1) * 136 + rl]     = __float2half(acc[mi][ni][1] + b1);
                st[cl * 136 + rl + 8]       = __float2half(acc[mi][ni][2] + b0);
                st[(cl + 1) * 136 + rl + 8] = __float2half(acc[mi][ni][3] + b1);
            }
        __syncthreads();
        const int b  = bm >> 11;          // batch (SEQ = 2048)
        const int s0 = bm & 2047;         // seq offset within batch
        const int col   = tid >> 1;       // 0..127 local h
        const int chunk = tid & 1;        // 64-row half
        const uint4* src = reinterpret_cast<const uint4*>(st + col * 136 + chunk * 64);
        uint4* dst = reinterpret_cast<uint4*>(
            C3h + ((long long)b * HDIM + cb + col) * SEQ + s0 + chunk * 64);
        #pragma unroll
        for (int i = 0; i < 8; i++) dst[i] = src[i];
        return;
    }

    #pragma unroll
    for (int mi = 0; mi < 4; mi++)
        #pragma unroll
        for (int ni = 0; ni < 4; ni++) {
            const int row = bm + wm + mi * 16 + r;
            const int col = cb + wn + ni * 8 + 2 * c;
            float v00 = acc[mi][ni][0], v01 = acc[mi][ni][1];
            float v10 = acc[mi][ni][2], v11 = acc[mi][ni][3];
            if (bias) {
                const float b0 = bias[col], b1 = bias[col + 1];
                v00 += b0; v01 += b1; v10 += b0; v11 += b1;
            }
            if (EPI == 0) {
                *reinterpret_cast<float2*>(Cf + (long long)row * stride + col)
                    = make_float2(v00, v01);
                *reinterpret_cast<float2*>(Cf + (long long)(row + 8) * stride + col)
                    = make_float2(v10, v11);
            } else {
                hf h0, l0, h1, l1;
                split1(v00, h0, l0); split1(v01, h1, l1);
                *reinterpret_cast<__half2*>(dh + (long long)row * stride + col)
                    = __halves2half2(h0, h1);
                *reinterpret_cast<__half2*>(dl + (long long)row * stride + col)
                    = __halves2half2(l0, l1);
                split1(v10, h0, l0); split1(v11, h1, l1);
                *reinterpret_cast<__half2*>(dh + (long long)(row + 8) * stride + col)
                    = __halves2half2(h0, h1);
                *reinterpret_cast<__half2*>(dl + (long long)(row + 8) * stride + col)
                    = __halves2half2(l0, l1);
            }
        }
}

// ---------------------------------------------------------------------------
// All input splits in ONE launch. grid.y selects the segment.
// ---------------------------------------------------------------------------
__global__ void __launch_bounds__(256) split_all(
    const float* __restrict__ x,  const float* __restrict__ wq,
    const float* __restrict__ wk, const float* __restrict__ wv,
    const float* __restrict__ wo,
    hf* __restrict__ xh, hf* __restrict__ xl,
    hf* __restrict__ wch, hf* __restrict__ wcl,
    hf* __restrict__ woh, hf* __restrict__ wol)
{
    const float* in; hf *h, *l; int n4;
    switch (blockIdx.y) {
        case 0: in = x;  h = xh;            l = xl;            n4 = MTOT * NDIM / 4; break;
        case 1: in = wq; h = wch;           l = wcl;           n4 = WSZ / 4; break;
        case 2: in = wk; h = wch + WSZ;     l = wcl + WSZ;     n4 = WSZ / 4; break;
        case 3: in = wv; h = wch + 2 * WSZ; l = wcl + 2 * WSZ; n4 = WSZ / 4; break;
        default:in = wo; h = woh;           l = wol;           n4 = WSZ / 4; break;
    }
    for (int i = blockIdx.x * blockDim.x + threadIdx.x; i < n4;
         i += gridDim.x * blockDim.x) {
        float4 v = reinterpret_cast<const float4*>(in)[i];
        hf h0,l0,h1,l1,h2,l2,h3,l3;
        split1(v.x, h0, l0); split1(v.y, h1, l1);
        split1(v.z, h2, l2); split1(v.w, h3, l3);
        reinterpret_cast<__half2*>(h)[2 * i]     = __halves2half2(h0, h1);
        reinterpret_cast<__half2*>(h)[2 * i + 1] = __halves2half2(h2, h3);
        reinterpret_cast<__half2*>(l)[2 * i]     = __halves2half2(l0, l1);
        reinterpret_cast<__half2*>(l)[2 * i + 1] = __halves2half2(l2, l3);
    }
}

// ---------------------------------------------------------------------------
// combine split-K partials -> single fp16 plane (y hi)
// ---------------------------------------------------------------------------
__global__ void __launch_bounds__(256) combine_h(
    const float* __restrict__ p0, const float* __restrict__ p1,
    hf* __restrict__ h, int n4)
{
    for (int i = blockIdx.x * blockDim.x + threadIdx.x; i < n4;
         i += gridDim.x * blockDim.x) {
        float4 a = reinterpret_cast<const float4*>(p0)[i];
        float4 b = reinterpret_cast<const float4*>(p1)[i];
        a.x += b.x; a.y += b.y; a.z += b.z; a.w += b.w;
        reinterpret_cast<__half2*>(h)[2 * i]     = __floats2half2_rn(a.x, a.y);
        reinterpret_cast<__half2*>(h)[2 * i + 1] = __floats2half2_rn(a.z, a.w);
    }
}

// ---------------------------------------------------------------------------
// Row softmax over SUM of two split-K partial planes -> fp16 probs
// ---------------------------------------------------------------------------
__global__ void __launch_bounds__(256) softmax_h2(
    const float* __restrict__ S0, const float* __restrict__ S1,
    hf* __restrict__ Ph)
{
    __shared__ float buf[SEQ];
    __shared__ float red[8];

    const int tid = threadIdx.x;
    const float2* r0 = reinterpret_cast<const float2*>(S0 + (long long)blockIdx.x * SEQ);
    const float2* r1 = reinterpret_cast<const float2*>(S1 + (long long)blockIdx.x * SEQ);
    float2* b2 = reinterpret_cast<float2*>(buf);

    float m = -1e30f;
    #pragma unroll
    for (int j = 0; j < 4; j++) {
        float2 fa = r0[tid + j * 256];
        float2 fb = r1[tid + j * 256];
        fa.x += fb.x; fa.y += fb.y;
        b2[tid + j * 256] = fa;
        m = fmaxf(m, fmaxf(fa.x, fa.y));
    }
    #pragma unroll
    for (int o = 16; o > 0; o >>= 1)
        m = fmaxf(m, __shfl_xor_sync(0xffffffffu, m, o));
    if ((tid & 31) == 0) red[tid >> 5] = m;
    __syncthreads();
    float bmax = red[0];
    #pragma unroll
    for (int w = 1; w < 8; w++) bmax = fmaxf(bmax, red[w]);
    __syncthreads();

    float s = 0.f;
    #pragma unroll
    for (int j = 0; j < 4; j++) {
        float2 f = b2[tid + j * 256];
        f.x = __expf(f.x - bmax);
        f.y = __expf(f.y - bmax);
        b2[tid + j * 256] = f;
        s += f.x + f.y;
    }
    #pragma unroll
    for (int o = 16; o > 0; o >>= 1)
        s += __shfl_xor_sync(0xffffffffu, s, o);
    if ((tid & 31) == 0) red[tid >> 5] = s;
    __syncthreads();
    float tot = 0.f;
    #pragma unroll
    for (int w = 0; w < 8; w++) tot += red[w];
    const float inv = 1.f / tot;

    __half2* ph2 = reinterpret_cast<__half2*>(Ph) + (long long)blockIdx.x * (SEQ / 2);
    #pragma unroll
    for (int j = 0; j < 4; j++) {
        float2 f = b2[tid + j * 256];
        ph2[tid + j * 256] = __floats2half2_rn(f.x * inv, f.y * inv);
    }
}

// ---------------------------------------------------------------------------
extern "C" void kernel_launch(void* const* d_in, const int* in_sizes, int n_in,
                              void* d_out, int out_size)
{
    const float* x  = (const float*)d_in[0];
    const float* wq = (const float*)d_in[1];
    const float* bq = (const float*)d_in[2];
    const float* wk = (const float*)d_in[3];
    const float* bk = (const float*)d_in[4];
    const float* wv = (const float*)d_in[5];
    const float* bv = (const float*)d_in[6];
    const float* wo = (const float*)d_in[7];
    const float* bo = (const float*)d_in[8];
    float* out = (float*)d_out;

    static bool attr_done = false;
    if (!attr_done) {
        cudaFuncSetAttribute((hfs_gemm<0,3>),  cudaFuncAttributeMaxDynamicSharedMemorySize, SMEM_BYTES);
        cudaFuncSetAttribute((hfs_gemm<0,1>),  cudaFuncAttributeMaxDynamicSharedMemorySize, SMEM_BYTES);
        cudaFuncSetAttribute((hfs_gemm<2,23>), cudaFuncAttributeMaxDynamicSharedMemorySize, SMEM_BYTES);
        attr_done = true;
    }

    hf *xh,*xl,*wch,*wcl,*woh,*wol;
    hf *qh,*ql,*kh,*kl,*vth,*sh,*yh;
    float *s, *py;
    cudaGetSymbolAddress((void**)&xh, g_xh);   cudaGetSymbolAddress((void**)&xl, g_xl);
    cudaGetSymbolAddress((void**)&wch, g_wch); cudaGetSymbolAddress((void**)&wcl, g_wcl);
    cudaGetSymbolAddress((void**)&woh, g_woh); cudaGetSymbolAddress((void**)&wol, g_wol);
    cudaGetSymbolAddress((void**)&qh, g_qh);   cudaGetSymbolAddress((void**)&ql, g_ql);
    cudaGetSymbolAddress((void**)&kh, g_kh);   cudaGetSymbolAddress((void**)&kl, g_kl);
    cudaGetSymbolAddress((void**)&vth, g_vth);
    cudaGetSymbolAddress((void**)&s, g_s);
    cudaGetSymbolAddress((void**)&sh, g_sh);
    cudaGetSymbolAddress((void**)&yh, g_yh);
    cudaGetSymbolAddress((void**)&py, g_py);

    const long long SPLANE = (long long)BATCH * SEQ * SEQ;
    const dim3 blk(256);

    // 0) all splits in one launch
    {
        dim3 grid(512, 5, 1);
        split_all<<<grid, blk>>>(x, wq, wk, wv, wo, xh, xl, wch, wcl, woh, wol);
    }

    // 1) fused QKV projection (q,k 3-term; v 1-term written transposed to vth)
    {
        dim3 grid(3 * HDIM / 128, MTOT / 128, 1);
        hfs_gemm<2,23><<<grid, blk, SMEM_BYTES>>>(
            xh, xl, wch, wcl, bq, bk, bv,
            nullptr, qh, ql, kh, kl, vth, vth,
            MTOT, 3 * HDIM, NDIM, NDIM, NDIM, HDIM, 1, 0, 0, 0, 0, 0, 0);
    }

    // 2) scores = Q K^T (fp32, 3-term, split-K=2 -> two partial planes)
    {
        dim3 grid(SEQ / 128, SEQ / 128, BATCH * 2);
        hfs_gemm<0,3><<<grid, blk, SMEM_BYTES>>>(
            qh, ql, kh, kl, nullptr, nullptr, nullptr,
            s, nullptr, nullptr, nullptr, nullptr, nullptr, nullptr,
            SEQ, SEQ, HDIM / 2, HDIM, HDIM, SEQ, 2,
            (long long)SEQ * HDIM, (long long)SEQ * HDIM, (long long)SEQ * SEQ,
            HDIM / 2, HDIM / 2, SPLANE);
    }

    // 3) softmax over (s0 + s1) -> fp16 probs  (combine folded in)
    softmax_h2<<<BATCH * SEQ, blk>>>(s, s + SPLANE, sh);

    // 4) y = P V  (1-term: P fp16 x V^T fp16; split-K=2)
    {
        dim3 grid(HDIM / 128, SEQ / 128, BATCH * 2);
        hfs_gemm<0,1><<<grid, blk, SMEM_BYTES>>>(
            sh, sh, vth, vth, nullptr, nullptr, nullptr,
            py, nullptr, nullptr, nullptr, nullptr, nullptr, nullptr,
            SEQ, HDIM, SEQ / 2, SEQ, SEQ, HDIM, 2,
            (long long)SEQ * SEQ, (long long)HDIM * SEQ, (long long)SEQ * HDIM,
            SEQ / 2, SEQ / 2, (long long)MTOT * HDIM);
    }
    combine_h<<<512, blk>>>(py, py + (long long)MTOT * HDIM, yh, MTOT * HDIM / 4);

    // 5) out = Y Wo^T + bo (1-term, no split-K, bias folded, direct fp32 write)
    {
        dim3 grid(NDIM / 128, MTOT / 128, 1);
        hfs_gemm<0,1><<<grid, blk, SMEM_BYTES>>>(
            yh, yh, woh, woh, bo, nullptr, nullptr,
            out, nullptr, nullptr, nullptr, nullptr, nullptr, nullptr,
            MTOT, NDIM, HDIM, HDIM, HDIM, NDIM, 1,
            0, 0, 0, 0, 0, 0);
    }
}

// round 16
// speedup vs baseline: 1.0275x; 1.0275x over previous
#include <cuda_runtime.h>
#include <cuda_fp16.h>
#include <stdint.h>
#include <math.h>

#define BATCH 4
#define SEQ   2048
#define NDIM  768
#define HDIM  768
#define MTOT  (BATCH * SEQ)
#define WSZ   (HDIM * NDIM)

typedef __half hf;

// ------------------------- scratch (allocation-free) ------------------------
__device__ __align__(16) hf    g_xh[MTOT * NDIM];
__device__ __align__(16) hf    g_xl[MTOT * NDIM];
__device__ __align__(16) hf    g_wch[3 * WSZ];   // concat wq|wk|wv planes
__device__ __align__(16) hf    g_wcl[3 * WSZ];
__device__ __align__(16) hf    g_woh[WSZ];
__device__ __align__(16) hf    g_wol[WSZ];
__device__ __align__(16) hf    g_qh[MTOT * HDIM];
__device__ __align__(16) hf    g_ql[MTOT * HDIM];
__device__ __align__(16) hf    g_kh[MTOT * HDIM];
__device__ __align__(16) hf    g_kl[MTOT * HDIM];
__device__ __align__(16) hf    g_vth[(long long)BATCH * HDIM * SEQ];
__device__ __align__(16) float g_s [(long long)BATCH * SEQ * SEQ];
__device__ __align__(16) hf    g_sh[(long long)BATCH * SEQ * SEQ];
__device__ __align__(16) hf    g_yh[MTOT * HDIM];
__device__ __align__(16) float g_py[2LL * MTOT * HDIM];   // PV split-K partials

// ------------------------------ helpers -------------------------------------
__device__ __forceinline__ void mma16816(float* d, const uint32_t* a, const uint32_t* b)
{
    asm volatile(
        "mma.sync.aligned.m16n8k16.row.col.f32.f16.f16.f32 "
        "{%0,%1,%2,%3},{%4,%5,%6,%7},{%8,%9},{%0,%1,%2,%3};\n"
        : "+f"(d[0]), "+f"(d[1]), "+f"(d[2]), "+f"(d[3])
        : "r"(a[0]), "r"(a[1]), "r"(a[2]), "r"(a[3]), "r"(b[0]), "r"(b[1]));
}

__device__ __forceinline__ void ldsm_x4(uint32_t* r, uint32_t addr)
{
    asm volatile("ldmatrix.sync.aligned.m8n8.x4.shared.b16 {%0,%1,%2,%3}, [%4];"
                 : "=r"(r[0]), "=r"(r[1]), "=r"(r[2]), "=r"(r[3]) : "r"(addr));
}

__device__ __forceinline__ void split1(float x, hf& h, hf& l)
{
    h = __float2half(x);
    l = __float2half(x - __half2float(h));
}

__device__ __forceinline__ void cpa16(uint32_t dst, const void* src)
{
    asm volatile("cp.async.cg.shared.global [%0], [%1], 16;\n" :: "r"(dst), "l"(src));
}
__device__ __forceinline__ void cpa_commit() { asm volatile("cp.async.commit_group;\n"); }
template <int N>
__device__ __forceinline__ void cpa_wait() { asm volatile("cp.async.wait_group %0;\n" :: "n"(N)); }

// smem geometry (uint32 words). Row = 16 data words (32 halves of k) + 4 pad.
#define RSTRIDE 20
#define PLANE_W (128 * RSTRIDE)
#define PLANE_B (PLANE_W * 4)                 // 10240 B
#define SMEM_NT4 (2 * 4 * PLANE_B)            // 81920 (2-stage, 4 planes)
#define SMEM_NT1 (3 * 2 * PLANE_B)            // 61440 (3-stage, 2 planes)

// ---------------------------------------------------------------------------
// Split-fp16 tensor-core GEMM: C = A * B^T (+bias), split-K capable.
// EPI=0: fp32 Cf (adds bias0 if non-null).
// EPI=2: fused-QKV: seg0/1 -> split q/k planes; seg2 -> v written TRANSPOSED
//        (fp16) into C3h=[B,HDIM,SEQ], bias folded.
// Terms:  NT=1: hh (2 smem planes, 3-stage pipeline, single sync per tile).
//         NT=3: hh+hl+lh.  NT=23: QKV fused — q/k 3-term, v 1-term.
//         (NT=3/23: 4 smem planes, 2-stage pipeline.)
// ---------------------------------------------------------------------------
template <int EPI, int NT>
__global__ void __launch_bounds__(256, 2) hfs_gemm(
    const hf* __restrict__ Ah, const hf* __restrict__ Al,
    const hf* __restrict__ Bh, const hf* __restrict__ Bl,
    const float* __restrict__ bias0, const float* __restrict__ bias1,
    const float* __restrict__ bias2,
    float* __restrict__ Cf,
    hf* __restrict__ Ch, hf* __restrict__ Cl,
    hf* __restrict__ C2h, hf* __restrict__ C2l,
    hf* __restrict__ C3h, hf* __restrict__ C3l,
    int M, int N, int Kloop, int lda, int ldb, int ldc,
    int nsplit,
    long long sA, long long sB, long long sC,
    long long kOffA, long long kOffB, long long sSplit)
{
    extern __shared__ uint32_t smem[];

    constexpr int NST   = (NT == 1) ? 3 : 2;            // pipeline stages
    constexpr int BOFFP = (NT == 1) ? 1 : 2;            // B-hi plane index
    constexpr int STG_B = ((NT == 1) ? 2 : 4) * PLANE_B;

    const int bz = blockIdx.z;
    const int batch = bz / nsplit;
    const int split = bz - batch * nsplit;

    Ah += (long long)batch * sA + split * kOffA;
    Al += (long long)batch * sA + split * kOffA;
    Bh += (long long)batch * sB + split * kOffB;
    Bl += (long long)batch * sB + split * kOffB;
    if (EPI == 0) Cf += (long long)batch * sC + split * sSplit;

    const int tid  = threadIdx.x;
    const int lane = tid & 31;
    const int warp = tid >> 5;
    const int bm = blockIdx.y * 128;
    const int bn = blockIdx.x * 128;
    const int wm = (warp & 1) * 64;
    const int wn = (warp >> 1) * 32;
    const int r = lane >> 2;
    const int c = lane & 3;

    const int seg = (EPI == 2) ? (bn / 768) : 0;
    // term flags (CTA-uniform)
    const bool aLo = (NT == 3) || (NT == 23 && seg < 2);
    const bool bLo = (NT == 23) ? (seg < 2) : (NT >= 2);

    // ---- loader mapping: thread -> row=tid/2, two 16B chunks per plane ----
    const int ld_row = tid >> 1;
    const int ld_c0  = (tid & 1) * 2;
    const hf* pAh = Ah + (long long)(bm + ld_row) * lda + ld_c0 * 8;
    const hf* pAl = Al + (long long)(bm + ld_row) * lda + ld_c0 * 8;
    const hf* pBh = Bh + (long long)(bn + ld_row) * ldb + ld_c0 * 8;
    const hf* pBl = Bl + (long long)(bn + ld_row) * ldb + ld_c0 * 8;

    uint32_t smem_u32;
    asm("{ .reg .u64 t; cvta.to.shared.u64 t, %1; cvt.u32.u64 %0, t; }"
        : "=r"(smem_u32) : "l"(smem));
    const uint32_t dst_base = smem_u32 + (ld_row * RSTRIDE + 4 * ld_c0) * 4;

    auto load_stage = [&](int stage, int k0) {
        const uint32_t d = dst_base + stage * STG_B;
        cpa16(d,                pAh + k0);
        cpa16(d + 16,           pAh + k0 + 8);
        if (NT != 1 && aLo) {
            cpa16(d + PLANE_B,      pAl + k0);
            cpa16(d + PLANE_B + 16, pAl + k0 + 8);
        }
        cpa16(d + BOFFP * PLANE_B,      pBh + k0);
        cpa16(d + BOFFP * PLANE_B + 16, pBh + k0 + 8);
        if (NT != 1 && bLo) {
            cpa16(d + 3 * PLANE_B,      pBl + k0);
            cpa16(d + 3 * PLANE_B + 16, pBl + k0 + 8);
        }
    };

    const uint32_t aOff = (((wm + (lane & 15)) * RSTRIDE + ((lane >> 4) << 2)) << 2);
    const uint32_t bOff = (((wn + (lane & 7) + ((lane >> 4) << 3)) * RSTRIDE
                            + (((lane >> 3) & 1) << 2)) << 2);

    float acc[4][4][4];
    #pragma unroll
    for (int i = 0; i < 4; i++)
        #pragma unroll
        for (int j = 0; j < 4; j++)
            #pragma unroll
            for (int e = 0; e < 4; e++) acc[i][j][e] = 0.f;

    const int T = Kloop / 32;

    load_stage(0, 0);  cpa_commit();
    if (T > 1) load_stage(1, 32);
    cpa_commit();

    for (int t = 0; t < T; t++) {
        cpa_wait<1>();
        __syncthreads();

        if (NT == 1) {
            // 3-stage: prefetch t+2 NOW (targets stage != both live stages)
            if (t + 2 < T) load_stage((t + 2) % 3, (t + 2) * 32);
            cpa_commit();
        }

        const uint32_t stage_base = smem_u32 + (t % NST) * STG_B;
        const uint32_t aBaseH = stage_base + aOff;
        const uint32_t aBaseL = aBaseH + PLANE_B;
        const uint32_t bBaseH = stage_base + BOFFP * PLANE_B + bOff;
        const uint32_t bBaseL = stage_base + 3 * PLANE_B + bOff;

        #pragma unroll
        for (int ks = 0; ks < 2; ks++) {
            const uint32_t kb = ks * 32;
            uint32_t aH[4][4], aL[4][4], bH[4][2], bL[4][2];
            #pragma unroll
            for (int mi = 0; mi < 4; mi++) {
                ldsm_x4(aH[mi], aBaseH + mi * (16 * RSTRIDE * 4) + kb);
                if (NT != 1 && aLo)
                    ldsm_x4(aL[mi], aBaseL + mi * (16 * RSTRIDE * 4) + kb);
            }
            #pragma unroll
            for (int np = 0; np < 2; np++) {
                uint32_t th[4];
                ldsm_x4(th, bBaseH + np * (16 * RSTRIDE * 4) + kb);
                bH[2*np][0] = th[0]; bH[2*np][1] = th[1];
                bH[2*np+1][0] = th[2]; bH[2*np+1][1] = th[3];
                if (NT != 1 && bLo) {
                    uint32_t tl[4];
                    ldsm_x4(tl, bBaseL + np * (16 * RSTRIDE * 4) + kb);
                    bL[2*np][0] = tl[0]; bL[2*np][1] = tl[1];
                    bL[2*np+1][0] = tl[2]; bL[2*np+1][1] = tl[3];
                }
            }
            #pragma unroll
            for (int mi = 0; mi < 4; mi++)
                #pragma unroll
                for (int ni = 0; ni < 4; ni++) {
                    mma16816(acc[mi][ni], aH[mi], bH[ni]);
                    if (NT != 1 && bLo) mma16816(acc[mi][ni], aH[mi], bL[ni]);
                    if (NT != 1 && aLo) mma16816(acc[mi][ni], aL[mi], bH[ni]);
                }
        }

        if (NT != 1) {
            __syncthreads();
            if (t + 2 < T) load_stage(t & 1, (t + 2) * 32);
            cpa_commit();
        }
    }

    // ---------------- epilogue ----------------
    const float* bias = bias0;
    hf* dh = Ch; hf* dl = Cl;
    int cb = bn;
    int stride = ldc;
    if (EPI == 2) {
        cb = bn - seg * 768;
        stride = 768;
        if (seg == 1) { bias = bias1; dh = C2h; dl = C2l; }
        else if (seg == 2) { bias = bias2; }
    }

    if (EPI == 2 && seg == 2) {
        // ---- v segment: bias + fp16, written TRANSPOSED into C3h[B,HDIM,SEQ]
        __syncthreads();   // all warps done with pipeline smem (LDSM complete)
        hf* st = reinterpret_cast<hf*>(smem);
        #pragma unroll
        for (int mi = 0; mi < 4; mi++)
            #pragma unroll
            for (int ni = 0; ni < 4; ni++) {
                const int rl = wm + mi * 16 + r;
                const int cl = wn + ni * 8 + 2 * c;
                const float b0 = bias[cb + cl], b1 = bias[cb + cl + 1];
                st[cl * 136 + rl]           = __float2half(acc[mi][ni][0] + b0);
                st[(cl + 1) * 136 + rl]     = __float2half(acc[mi][ni][1] + b1);
                st[cl * 136 + rl + 8]       = __float2half(acc[mi][ni][2] + b0);
                st[(cl + 1) * 136 + rl + 8] = __float2half(acc[mi][ni][3] + b1);
            }
        __syncthreads();
        const int b  = bm >> 11;          // batch (SEQ = 2048)
        const int s0 = bm & 2047;         // seq offset within batch
        const int col   = tid >> 1;       // 0..127 local h
        const int chunk = tid & 1;        // 64-row half
        const uint4* src = reinterpret_cast<const uint4*>(st + col * 136 + chunk * 64);
        uint4* dst = reinterpret_cast<uint4*>(
            C3h + ((long long)b * HDIM + cb + col) * SEQ + s0 + chunk * 64);
        #pragma unroll
        for (int i = 0; i < 8; i++) dst[i] = src[i];
        return;
    }

    #pragma unroll
    for (int mi = 0; mi < 4; mi++)
        #pragma unroll
        for (int ni = 0; ni < 4; ni++) {
            const int row = bm + wm + mi * 16 + r;
            const int col = cb + wn + ni * 8 + 2 * c;
            float v00 = acc[mi][ni][0], v01 = acc[mi][ni][1];
            float v10 = acc[mi][ni][2], v11 = acc[mi][ni][3];
            if (bias) {
                const float b0 = bias[col], b1 = bias[col + 1];
                v00 += b0; v01 += b1; v10 += b0; v11 += b1;
            }
            if (EPI == 0) {
                *reinterpret_cast<float2*>(Cf + (long long)row * stride + col)
                    = make_float2(v00, v01);
                *reinterpret_cast<float2*>(Cf + (long long)(row + 8) * stride + col)
                    = make_float2(v10, v11);
            } else {
                hf h0, l0, h1, l1;
                split1(v00, h0, l0); split1(v01, h1, l1);
                *reinterpret_cast<__half2*>(dh + (long long)row * stride + col)
                    = __halves2half2(h0, h1);
                *reinterpret_cast<__half2*>(dl + (long long)row * stride + col)
                    = __halves2half2(l0, l1);
                split1(v10, h0, l0); split1(v11, h1, l1);
                *reinterpret_cast<__half2*>(dh + (long long)(row + 8) * stride + col)
                    = __halves2half2(h0, h1);
                *reinterpret_cast<__half2*>(dl + (long long)(row + 8) * stride + col)
                    = __halves2half2(l0, l1);
            }
        }
}

// ---------------------------------------------------------------------------
// All input splits in ONE launch. grid.y selects the segment.
// ---------------------------------------------------------------------------
__global__ void __launch_bounds__(256) split_all(
    const float* __restrict__ x,  const float* __restrict__ wq,
    const float* __restrict__ wk, const float* __restrict__ wv,
    const float* __restrict__ wo,
    hf* __restrict__ xh, hf* __restrict__ xl,
    hf* __restrict__ wch, hf* __restrict__ wcl,
    hf* __restrict__ woh, hf* __restrict__ wol)
{
    const float* in; hf *h, *l; int n4;
    switch (blockIdx.y) {
        case 0: in = x;  h = xh;            l = xl;            n4 = MTOT * NDIM / 4; break;
        case 1: in = wq; h = wch;           l = wcl;           n4 = WSZ / 4; break;
        case 2: in = wk; h = wch + WSZ;     l = wcl + WSZ;     n4 = WSZ / 4; break;
        case 3: in = wv; h = wch + 2 * WSZ; l = wcl + 2 * WSZ; n4 = WSZ / 4; break;
        default:in = wo; h = woh;           l = wol;           n4 = WSZ / 4; break;
    }
    for (int i = blockIdx.x * blockDim.x + threadIdx.x; i < n4;
         i += gridDim.x * blockDim.x) {
        float4 v = reinterpret_cast<const float4*>(in)[i];
        hf h0,l0,h1,l1,h2,l2,h3,l3;
        split1(v.x, h0, l0); split1(v.y, h1, l1);
        split1(v.z, h2, l2); split1(v.w, h3, l3);
        reinterpret_cast<__half2*>(h)[2 * i]     = __halves2half2(h0, h1);
        reinterpret_cast<__half2*>(h)[2 * i + 1] = __halves2half2(h2, h3);
        reinterpret_cast<__half2*>(l)[2 * i]     = __halves2half2(l0, l1);
        reinterpret_cast<__half2*>(l)[2 * i + 1] = __halves2half2(l2, l3);
    }
}

// ---------------------------------------------------------------------------
// combine split-K partials -> single fp16 plane (y hi)
// ---------------------------------------------------------------------------
__global__ void __launch_bounds__(256) combine_h(
    const float* __restrict__ p0, const float* __restrict__ p1,
    hf* __restrict__ h, int n4)
{
    for (int i = blockIdx.x * blockDim.x + threadIdx.x; i < n4;
         i += gridDim.x * blockDim.x) {
        float4 a = reinterpret_cast<const float4*>(p0)[i];
        float4 b = reinterpret_cast<const float4*>(p1)[i];
        a.x += b.x; a.y += b.y; a.z += b.z; a.w += b.w;
        reinterpret_cast<__half2*>(h)[2 * i]     = __floats2half2_rn(a.x, a.y);
        reinterpret_cast<__half2*>(h)[2 * i + 1] = __floats2half2_rn(a.z, a.w);
    }
}

// ---------------------------------------------------------------------------
// Row softmax: fp32 scores -> fp16 probs
// ---------------------------------------------------------------------------
__global__ void __launch_bounds__(256) softmax_h(
    const float* __restrict__ S, hf* __restrict__ Ph)
{
    __shared__ float buf[SEQ];
    __shared__ float red[8];

    const int tid = threadIdx.x;
    const float2* row2 = reinterpret_cast<const float2*>(S + (long long)blockIdx.x * SEQ);
    float2* b2 = reinterpret_cast<float2*>(buf);

    float m = -1e30f;
    #pragma unroll
    for (int j = 0; j < 4; j++) {
        float2 f = row2[tid + j * 256];
        b2[tid + j * 256] = f;
        m = fmaxf(m, fmaxf(f.x, f.y));
    }
    #pragma unroll
    for (int o = 16; o > 0; o >>= 1)
        m = fmaxf(m, __shfl_xor_sync(0xffffffffu, m, o));
    if ((tid & 31) == 0) red[tid >> 5] = m;
    __syncthreads();
    float bmax = red[0];
    #pragma unroll
    for (int w = 1; w < 8; w++) bmax = fmaxf(bmax, red[w]);
    __syncthreads();

    float s = 0.f;
    #pragma unroll
    for (int j = 0; j < 4; j++) {
        float2 f = b2[tid + j * 256];
        f.x = __expf(f.x - bmax);
        f.y = __expf(f.y - bmax);
        b2[tid + j * 256] = f;
        s += f.x + f.y;
    }
    #pragma unroll
    for (int o = 16; o > 0; o >>= 1)
        s += __shfl_xor_sync(0xffffffffu, s, o);
    if ((tid & 31) == 0) red[tid >> 5] = s;
    __syncthreads();
    float tot = 0.f;
    #pragma unroll
    for (int w = 0; w < 8; w++) tot += red[w];
    const float inv = 1.f / tot;

    __half2* ph2 = reinterpret_cast<__half2*>(Ph) + (long long)blockIdx.x * (SEQ / 2);
    #pragma unroll
    for (int j = 0; j < 4; j++) {
        float2 f = b2[tid + j * 256];
        ph2[tid + j * 256] = __floats2half2_rn(f.x * inv, f.y * inv);
    }
}

// ---------------------------------------------------------------------------
extern "C" void kernel_launch(void* const* d_in, const int* in_sizes, int n_in,
                              void* d_out, int out_size)
{
    const float* x  = (const float*)d_in[0];
    const float* wq = (const float*)d_in[1];
    const float* bq = (const float*)d_in[2];
    const float* wk = (const float*)d_in[3];
    const float* bk = (const float*)d_in[4];
    const float* wv = (const float*)d_in[5];
    const float* bv = (const float*)d_in[6];
    const float* wo = (const float*)d_in[7];
    const float* bo = (const float*)d_in[8];
    float* out = (float*)d_out;

    static bool attr_done = false;
    if (!attr_done) {
        cudaFuncSetAttribute((hfs_gemm<0,3>),  cudaFuncAttributeMaxDynamicSharedMemorySize, SMEM_NT4);
        cudaFuncSetAttribute((hfs_gemm<0,1>),  cudaFuncAttributeMaxDynamicSharedMemorySize, SMEM_NT1);
        cudaFuncSetAttribute((hfs_gemm<2,23>), cudaFuncAttributeMaxDynamicSharedMemorySize, SMEM_NT4);
        attr_done = true;
    }

    hf *xh,*xl,*wch,*wcl,*woh,*wol;
    hf *qh,*ql,*kh,*kl,*vth,*sh,*yh;
    float *s, *py;
    cudaGetSymbolAddress((void**)&xh, g_xh);   cudaGetSymbolAddress((void**)&xl, g_xl);
    cudaGetSymbolAddress((void**)&wch, g_wch); cudaGetSymbolAddress((void**)&wcl, g_wcl);
    cudaGetSymbolAddress((void**)&woh, g_woh); cudaGetSymbolAddress((void**)&wol, g_wol);
    cudaGetSymbolAddress((void**)&qh, g_qh);   cudaGetSymbolAddress((void**)&ql, g_ql);
    cudaGetSymbolAddress((void**)&kh, g_kh);   cudaGetSymbolAddress((void**)&kl, g_kl);
    cudaGetSymbolAddress((void**)&vth, g_vth);
    cudaGetSymbolAddress((void**)&s, g_s);
    cudaGetSymbolAddress((void**)&sh, g_sh);
    cudaGetSymbolAddress((void**)&yh, g_yh);
    cudaGetSymbolAddress((void**)&py, g_py);

    const dim3 blk(256);

    // 0) all splits in one launch
    {
        dim3 grid(512, 5, 1);
        split_all<<<grid, blk>>>(x, wq, wk, wv, wo, xh, xl, wch, wcl, woh, wol);
    }

    // 1) fused QKV projection (q,k 3-term; v 1-term written transposed to vth)
    {
        dim3 grid(3 * HDIM / 128, MTOT / 128, 1);
        hfs_gemm<2,23><<<grid, blk, SMEM_NT4>>>(
            xh, xl, wch, wcl, bq, bk, bv,
            nullptr, qh, ql, kh, kl, vth, vth,
            MTOT, 3 * HDIM, NDIM, NDIM, NDIM, HDIM, 1, 0, 0, 0, 0, 0, 0);
    }

    // 2) scores = Q K^T (fp32, 3-term, single launch — split-K regressed in R15)
    {
        dim3 grid(SEQ / 128, SEQ / 128, BATCH);
        hfs_gemm<0,3><<<grid, blk, SMEM_NT4>>>(
            qh, ql, kh, kl, nullptr, nullptr, nullptr,
            s, nullptr, nullptr, nullptr, nullptr, nullptr, nullptr,
            SEQ, SEQ, HDIM, HDIM, HDIM, SEQ, 1,
            (long long)SEQ * HDIM, (long long)SEQ * HDIM, (long long)SEQ * SEQ,
            0, 0, 0);
    }

    // 3) softmax -> fp16 probs
    softmax_h<<<BATCH * SEQ, blk>>>(s, sh);

    // 4) y = P V  (1-term, 3-stage pipeline; split-K=2)
    {
        dim3 grid(HDIM / 128, SEQ / 128, BATCH * 2);
        hfs_gemm<0,1><<<grid, blk, SMEM_NT1>>>(
            sh, sh, vth, vth, nullptr, nullptr, nullptr,
            py, nullptr, nullptr, nullptr, nullptr, nullptr, nullptr,
            SEQ, HDIM, SEQ / 2, SEQ, SEQ, HDIM, 2,
            (long long)SEQ * SEQ, (long long)HDIM * SEQ, (long long)SEQ * HDIM,
            SEQ / 2, SEQ / 2, (long long)MTOT * HDIM);
    }
    combine_h<<<512, blk>>>(py, py + (long long)MTOT * HDIM, yh, MTOT * HDIM / 4);

    // 5) out = Y Wo^T + bo (1-term, 3-stage pipeline, bias folded, direct write)
    {
        dim3 grid(NDIM / 128, MTOT / 128, 1);
        hfs_gemm<0,1><<<grid, blk, SMEM_NT1>>>(
            yh, yh, woh, woh, bo, nullptr, nullptr,
            out, nullptr, nullptr, nullptr, nullptr, nullptr, nullptr,
            MTOT, NDIM, HDIM, HDIM, HDIM, NDIM, 1,
            0, 0, 0, 0, 0, 0);
    }
}

// round 17
// speedup vs baseline: 1.0535x; 1.0254x over previous
#include <cuda_runtime.h>
#include <cuda_fp16.h>
#include <stdint.h>
#include <math.h>

#define BATCH 4
#define SEQ   2048
#define NDIM  768
#define HDIM  768
#define MTOT  (BATCH * SEQ)
#define WSZ   (HDIM * NDIM)

typedef __half hf;

// ------------------------- scratch (allocation-free) ------------------------
__device__ __align__(16) hf    g_xh[MTOT * NDIM];
__device__ __align__(16) hf    g_xl[MTOT * NDIM];
__device__ __align__(16) hf    g_wch[3 * WSZ];   // concat wq|wk|wv planes
__device__ __align__(16) hf    g_wcl[3 * WSZ];
__device__ __align__(16) hf    g_woh[WSZ];
__device__ __align__(16) hf    g_wol[WSZ];
__device__ __align__(16) hf    g_qh[MTOT * HDIM];
__device__ __align__(16) hf    g_ql[MTOT * HDIM];
__device__ __align__(16) hf    g_kh[MTOT * HDIM];
__device__ __align__(16) hf    g_kl[MTOT * HDIM];
__device__ __align__(16) hf    g_vth[(long long)BATCH * HDIM * SEQ];
__device__ __align__(16) float g_s [(long long)BATCH * SEQ * SEQ];
__device__ __align__(16) hf    g_sh[(long long)BATCH * SEQ * SEQ];
__device__ __align__(16) hf    g_yh[MTOT * HDIM];
__device__ __align__(16) float g_py[2LL * MTOT * HDIM];   // PV split-K partials

// ------------------------------ helpers -------------------------------------
__device__ __forceinline__ void mma16816(float* d, const uint32_t* a, const uint32_t* b)
{
    asm volatile(
        "mma.sync.aligned.m16n8k16.row.col.f32.f16.f16.f32 "
        "{%0,%1,%2,%3},{%4,%5,%6,%7},{%8,%9},{%0,%1,%2,%3};\n"
        : "+f"(d[0]), "+f"(d[1]), "+f"(d[2]), "+f"(d[3])
        : "r"(a[0]), "r"(a[1]), "r"(a[2]), "r"(a[3]), "r"(b[0]), "r"(b[1]));
}

__device__ __forceinline__ void ldsm_x4(uint32_t* r, uint32_t addr)
{
    asm volatile("ldmatrix.sync.aligned.m8n8.x4.shared.b16 {%0,%1,%2,%3}, [%4];"
                 : "=r"(r[0]), "=r"(r[1]), "=r"(r[2]), "=r"(r[3]) : "r"(addr));
}

__device__ __forceinline__ void split1(float x, hf& h, hf& l)
{
    h = __float2half(x);
    l = __float2half(x - __half2float(h));
}

__device__ __forceinline__ void cpa16(uint32_t dst, const void* src)
{
    asm volatile("cp.async.cg.shared.global [%0], [%1], 16;\n" :: "r"(dst), "l"(src));
}
__device__ __forceinline__ void cpa_commit() { asm volatile("cp.async.commit_group;\n"); }
template <int N>
__device__ __forceinline__ void cpa_wait() { asm volatile("cp.async.wait_group %0;\n" :: "n"(N)); }

// smem geometry (uint32 words). Row = 16 data words (32 halves of k) + 4 pad.
#define RSTRIDE 20
#define PLANE_W (128 * RSTRIDE)
#define PLANE_B (PLANE_W * 4)                 // 10240 B
#define SMEM_NT4 (2 * 4 * PLANE_B)            // 81920 (2-stage, 4 planes)
#define SMEM_NT1 (3 * 2 * PLANE_B)            // 61440 (3-stage, 2 planes)

// ---------------------------------------------------------------------------
// Split-fp16 tensor-core GEMM: C = A * B^T (+bias), split-K capable.
// EPI=0: fp32 Cf (adds bias0 if non-null).
// EPI=2: fused-QKV: CTA launch order remapped so the 768 heavy q/k CTAs get
//        linear ids 0..767 and the 384 cheap v CTAs drain the tail.
//        seg0/1 -> split q/k planes; seg2 -> v written TRANSPOSED (fp16) into
//        C3h=[B,HDIM,SEQ], bias folded.
// Terms:  NT=1: hh (2 smem planes, 3-stage pipeline, single sync per tile).
//         NT=3: hh+hl+lh.  NT=23: QKV fused — q/k 3-term, v 1-term.
// ---------------------------------------------------------------------------
template <int EPI, int NT>
__global__ void __launch_bounds__(256, 2) hfs_gemm(
    const hf* __restrict__ Ah, const hf* __restrict__ Al,
    const hf* __restrict__ Bh, const hf* __restrict__ Bl,
    const float* __restrict__ bias0, const float* __restrict__ bias1,
    const float* __restrict__ bias2,
    float* __restrict__ Cf,
    hf* __restrict__ Ch, hf* __restrict__ Cl,
    hf* __restrict__ C2h, hf* __restrict__ C2l,
    hf* __restrict__ C3h, hf* __restrict__ C3l,
    int M, int N, int Kloop, int lda, int ldb, int ldc,
    int nsplit,
    long long sA, long long sB, long long sC,
    long long kOffA, long long kOffB, long long sSplit)
{
    extern __shared__ uint32_t smem[];

    constexpr int NST   = (NT == 1) ? 3 : 2;            // pipeline stages
    constexpr int BOFFP = (NT == 1) ? 1 : 2;            // B-hi plane index
    constexpr int STG_B = ((NT == 1) ? 2 : 4) * PLANE_B;

    const int bz = blockIdx.z;
    const int batch = bz / nsplit;
    const int split = bz - batch * nsplit;

    Ah += (long long)batch * sA + split * kOffA;
    Al += (long long)batch * sA + split * kOffA;
    Bh += (long long)batch * sB + split * kOffB;
    Bl += (long long)batch * sB + split * kOffB;
    if (EPI == 0) Cf += (long long)batch * sC + split * sSplit;

    const int tid  = threadIdx.x;
    const int lane = tid & 31;
    const int warp = tid >> 5;

    // ---- CTA tile origin ----
    int bm, bn;
    if (EPI == 2) {
        // launch-order remap: heavy q/k CTAs first (lin 0..767), v CTAs last.
        const int lin = blockIdx.y * gridDim.x + blockIdx.x;   // launch order
        if (lin < 768) { bn = (lin % 12) * 128; bm = (lin / 12) * 128; }
        else { const int l2 = lin - 768; bn = 1536 + (l2 % 6) * 128; bm = (l2 / 6) * 128; }
    } else {
        bm = blockIdx.y * 128;
        bn = blockIdx.x * 128;
    }
    const int wm = (warp & 1) * 64;
    const int wn = (warp >> 1) * 32;
    const int r = lane >> 2;
    const int c = lane & 3;

    const int seg = (EPI == 2) ? (bn / 768) : 0;
    // term flags (CTA-uniform)
    const bool aLo = (NT == 3) || (NT == 23 && seg < 2);
    const bool bLo = (NT == 23) ? (seg < 2) : (NT >= 2);

    // ---- loader mapping: thread -> row=tid/2, two 16B chunks per plane ----
    const int ld_row = tid >> 1;
    const int ld_c0  = (tid & 1) * 2;
    const hf* pAh = Ah + (long long)(bm + ld_row) * lda + ld_c0 * 8;
    const hf* pAl = Al + (long long)(bm + ld_row) * lda + ld_c0 * 8;
    const hf* pBh = Bh + (long long)(bn + ld_row) * ldb + ld_c0 * 8;
    const hf* pBl = Bl + (long long)(bn + ld_row) * ldb + ld_c0 * 8;

    uint32_t smem_u32;
    asm("{ .reg .u64 t; cvta.to.shared.u64 t, %1; cvt.u32.u64 %0, t; }"
        : "=r"(smem_u32) : "l"(smem));
    const uint32_t dst_base = smem_u32 + (ld_row * RSTRIDE + 4 * ld_c0) * 4;

    auto load_stage = [&](int stage, int k0) {
        const uint32_t d = dst_base + stage * STG_B;
        cpa16(d,                pAh + k0);
        cpa16(d + 16,           pAh + k0 + 8);
        if (NT != 1 && aLo) {
            cpa16(d + PLANE_B,      pAl + k0);
            cpa16(d + PLANE_B + 16, pAl + k0 + 8);
        }
        cpa16(d + BOFFP * PLANE_B,      pBh + k0);
        cpa16(d + BOFFP * PLANE_B + 16, pBh + k0 + 8);
        if (NT != 1 && bLo) {
            cpa16(d + 3 * PLANE_B,      pBl + k0);
            cpa16(d + 3 * PLANE_B + 16, pBl + k0 + 8);
        }
    };

    const uint32_t aOff = (((wm + (lane & 15)) * RSTRIDE + ((lane >> 4) << 2)) << 2);
    const uint32_t bOff = (((wn + (lane & 7) + ((lane >> 4) << 3)) * RSTRIDE
                            + (((lane >> 3) & 1) << 2)) << 2);

    float acc[4][4][4];
    #pragma unroll
    for (int i = 0; i < 4; i++)
        #pragma unroll
        for (int j = 0; j < 4; j++)
            #pragma unroll
            for (int e = 0; e < 4; e++) acc[i][j][e] = 0.f;

    const int T = Kloop / 32;

    load_stage(0, 0);  cpa_commit();
    if (T > 1) load_stage(1, 32);
    cpa_commit();

    for (int t = 0; t < T; t++) {
        cpa_wait<1>();
        __syncthreads();

        if (NT == 1) {
            if (t + 2 < T) load_stage((t + 2) % 3, (t + 2) * 32);
            cpa_commit();
        }

        const uint32_t stage_base = smem_u32 + (t % NST) * STG_B;
        const uint32_t aBaseH = stage_base + aOff;
        const uint32_t aBaseL = aBaseH + PLANE_B;
        const uint32_t bBaseH = stage_base + BOFFP * PLANE_B + bOff;
        const uint32_t bBaseL = stage_base + 3 * PLANE_B + bOff;

        #pragma unroll
        for (int ks = 0; ks < 2; ks++) {
            const uint32_t kb = ks * 32;
            uint32_t aH[4][4], aL[4][4], bH[4][2], bL[4][2];
            #pragma unroll
            for (int mi = 0; mi < 4; mi++) {
                ldsm_x4(aH[mi], aBaseH + mi * (16 * RSTRIDE * 4) + kb);
                if (NT != 1 && aLo)
                    ldsm_x4(aL[mi], aBaseL + mi * (16 * RSTRIDE * 4) + kb);
            }
            #pragma unroll
            for (int np = 0; np < 2; np++) {
                uint32_t th[4];
                ldsm_x4(th, bBaseH + np * (16 * RSTRIDE * 4) + kb);
                bH[2*np][0] = th[0]; bH[2*np][1] = th[1];
                bH[2*np+1][0] = th[2]; bH[2*np+1][1] = th[3];
                if (NT != 1 && bLo) {
                    uint32_t tl[4];
                    ldsm_x4(tl, bBaseL + np * (16 * RSTRIDE * 4) + kb);
                    bL[2*np][0] = tl[0]; bL[2*np][1] = tl[1];
                    bL[2*np+1][0] = tl[2]; bL[2*np+1][1] = tl[3];
                }
            }
            #pragma unroll
            for (int mi = 0; mi < 4; mi++)
                #pragma unroll
                for (int ni = 0; ni < 4; ni++) {
                    mma16816(acc[mi][ni], aH[mi], bH[ni]);
                    if (NT != 1 && bLo) mma16816(acc[mi][ni], aH[mi], bL[ni]);
                    if (NT != 1 && aLo) mma16816(acc[mi][ni], aL[mi], bH[ni]);
                }
        }

        if (NT != 1) {
            __syncthreads();
            if (t + 2 < T) load_stage(t & 1, (t + 2) * 32);
            cpa_commit();
        }
    }

    // ---------------- epilogue ----------------
    const float* bias = bias0;
    hf* dh = Ch; hf* dl = Cl;
    int cb = bn;
    int stride = ldc;
    if (EPI == 2) {
        cb = bn - seg * 768;
        stride = 768;
        if (seg == 1) { bias = bias1; dh = C2h; dl = C2l; }
        else if (seg == 2) { bias = bias2; }
    }

    if (EPI == 2 && seg == 2) {
        // ---- v segment: bias + fp16, written TRANSPOSED into C3h[B,HDIM,SEQ]
        __syncthreads();   // all warps done with pipeline smem (LDSM complete)
        hf* st = reinterpret_cast<hf*>(smem);
        #pragma unroll
        for (int mi = 0; mi < 4; mi++)
            #pragma unroll
            for (int ni = 0; ni < 4; ni++) {
                const int rl = wm + mi * 16 + r;
                const int cl = wn + ni * 8 + 2 * c;
                const float b0 = bias[cb + cl], b1 = bias[cb + cl + 1];
                st[cl * 136 + rl]           = __float2half(acc[mi][ni][0] + b0);
                st[(cl + 1) * 136 + rl]     = __float2half(acc[mi][ni][1] + b1);
                st[cl * 136 + rl + 8]       = __float2half(acc[mi][ni][2] + b0);
                st[(cl + 1) * 136 + rl + 8] = __float2half(acc[mi][ni][3] + b1);
            }
        __syncthreads();
        const int b  = bm >> 11;          // batch (SEQ = 2048)
        const int s0 = bm & 2047;         // seq offset within batch
        const int col   = tid >> 1;       // 0..127 local h
        const int chunk = tid & 1;        // 64-row half
        const uint4* src = reinterpret_cast<const uint4*>(st + col * 136 + chunk * 64);
        uint4* dst = reinterpret_cast<uint4*>(
            C3h + ((long long)b * HDIM + cb + col) * SEQ + s0 + chunk * 64);
        #pragma unroll
        for (int i = 0; i < 8; i++) dst[i] = src[i];
        return;
    }

    #pragma unroll
    for (int mi = 0; mi < 4; mi++)
        #pragma unroll
        for (int ni = 0; ni < 4; ni++) {
            const int row = bm + wm + mi * 16 + r;
            const int col = cb + wn + ni * 8 + 2 * c;
            float v00 = acc[mi][ni][0], v01 = acc[mi][ni][1];
            float v10 = acc[mi][ni][2], v11 = acc[mi][ni][3];
            if (bias) {
                const float b0 = bias[col], b1 = bias[col + 1];
                v00 += b0; v01 += b1; v10 += b0; v11 += b1;
            }
            if (EPI == 0) {
                *reinterpret_cast<float2*>(Cf + (long long)row * stride + col)
                    = make_float2(v00, v01);
                *reinterpret_cast<float2*>(Cf + (long long)(row + 8) * stride + col)
                    = make_float2(v10, v11);
            } else {
                hf h0, l0, h1, l1;
                split1(v00, h0, l0); split1(v01, h1, l1);
                *reinterpret_cast<__half2*>(dh + (long long)row * stride + col)
                    = __halves2half2(h0, h1);
                *reinterpret_cast<__half2*>(dl + (long long)row * stride + col)
                    = __halves2half2(l0, l1);
                split1(v10, h0, l0); split1(v11, h1, l1);
                *reinterpret_cast<__half2*>(dh + (long long)(row + 8) * stride + col)
                    = __halves2half2(h0, h1);
                *reinterpret_cast<__half2*>(dl + (long long)(row + 8) * stride + col)
                    = __halves2half2(l0, l1);
            }
        }
}

// ---------------------------------------------------------------------------
// All input splits in ONE launch. grid.y selects the segment.
// ---------------------------------------------------------------------------
__global__ void __launch_bounds__(256) split_all(
    const float* __restrict__ x,  const float* __restrict__ wq,
    const float* __restrict__ wk, const float* __restrict__ wv,
    const float* __restrict__ wo,
    hf* __restrict__ xh, hf* __restrict__ xl,
    hf* __restrict__ wch, hf* __restrict__ wcl,
    hf* __restrict__ woh, hf* __restrict__ wol)
{
    const float* in; hf *h, *l; int n4;
    switch (blockIdx.y) {
        case 0: in = x;  h = xh;            l = xl;            n4 = MTOT * NDIM / 4; break;
        case 1: in = wq; h = wch;           l = wcl;           n4 = WSZ / 4; break;
        case 2: in = wk; h = wch + WSZ;     l = wcl + WSZ;     n4 = WSZ / 4; break;
        case 3: in = wv; h = wch + 2 * WSZ; l = wcl + 2 * WSZ; n4 = WSZ / 4; break;
        default:in = wo; h = woh;           l = wol;           n4 = WSZ / 4; break;
    }
    for (int i = blockIdx.x * blockDim.x + threadIdx.x; i < n4;
         i += gridDim.x * blockDim.x) {
        float4 v = reinterpret_cast<const float4*>(in)[i];
        hf h0,l0,h1,l1,h2,l2,h3,l3;
        split1(v.x, h0, l0); split1(v.y, h1, l1);
        split1(v.z, h2, l2); split1(v.w, h3, l3);
        reinterpret_cast<__half2*>(h)[2 * i]     = __halves2half2(h0, h1);
        reinterpret_cast<__half2*>(h)[2 * i + 1] = __halves2half2(h2, h3);
        reinterpret_cast<__half2*>(l)[2 * i]     = __halves2half2(l0, l1);
        reinterpret_cast<__half2*>(l)[2 * i + 1] = __halves2half2(l2, l3);
    }
}

// ---------------------------------------------------------------------------
// combine split-K partials -> single fp16 plane (y hi)
// ---------------------------------------------------------------------------
__global__ void __launch_bounds__(256) combine_h(
    const float* __restrict__ p0, const float* __restrict__ p1,
    hf* __restrict__ h, int n4)
{
    for (int i = blockIdx.x * blockDim.x + threadIdx.x; i < n4;
         i += gridDim.x * blockDim.x) {
        float4 a = reinterpret_cast<const float4*>(p0)[i];
        float4 b = reinterpret_cast<const float4*>(p1)[i];
        a.x += b.x; a.y += b.y; a.z += b.z; a.w += b.w;
        reinterpret_cast<__half2*>(h)[2 * i]     = __floats2half2_rn(a.x, a.y);
        reinterpret_cast<__half2*>(h)[2 * i + 1] = __floats2half2_rn(a.z, a.w);
    }
}

// ---------------------------------------------------------------------------
// Row softmax: fp32 scores -> fp16 probs
// ---------------------------------------------------------------------------
__global__ void __launch_bounds__(256) softmax_h(
    const float* __restrict__ S, hf* __restrict__ Ph)
{
    __shared__ float buf[SEQ];
    __shared__ float red[8];

    const int tid = threadIdx.x;
    const float2* row2 = reinterpret_cast<const float2*>(S + (long long)blockIdx.x * SEQ);
    float2* b2 = reinterpret_cast<float2*>(buf);

    float m = -1e30f;
    #pragma unroll
    for (int j = 0; j < 4; j++) {
        float2 f = row2[tid + j * 256];
        b2[tid + j * 256] = f;
        m = fmaxf(m, fmaxf(f.x, f.y));
    }
    #pragma unroll
    for (int o = 16; o > 0; o >>= 1)
        m = fmaxf(m, __shfl_xor_sync(0xffffffffu, m, o));
    if ((tid & 31) == 0) red[tid >> 5] = m;
    __syncthreads();
    float bmax = red[0];
    #pragma unroll
    for (int w = 1; w < 8; w++) bmax = fmaxf(bmax, red[w]);
    __syncthreads();

    float s = 0.f;
    #pragma unroll
    for (int j = 0; j < 4; j++) {
        float2 f = b2[tid + j * 256];
        f.x = __expf(f.x - bmax);
        f.y = __expf(f.y - bmax);
        b2[tid + j * 256] = f;
        s += f.x + f.y;
    }
    #pragma unroll
    for (int o = 16; o > 0; o >>= 1)
        s += __shfl_xor_sync(0xffffffffu, s, o);
    if ((tid & 31) == 0) red[tid >> 5] = s;
    __syncthreads();
    float tot = 0.f;
    #pragma unroll
    for (int w = 0; w < 8; w++) tot += red[w];
    const float inv = 1.f / tot;

    __half2* ph2 = reinterpret_cast<__half2*>(Ph) + (long long)blockIdx.x * (SEQ / 2);
    #pragma unroll
    for (int j = 0; j < 4; j++) {
        float2 f = b2[tid + j * 256];
        ph2[tid + j * 256] = __floats2half2_rn(f.x * inv, f.y * inv);
    }
}

// ---------------------------------------------------------------------------
extern "C" void kernel_launch(void* const* d_in, const int* in_sizes, int n_in,
                              void* d_out, int out_size)
{
    const float* x  = (const float*)d_in[0];
    const float* wq = (const float*)d_in[1];
    const float* bq = (const float*)d_in[2];
    const float* wk = (const float*)d_in[3];
    const float* bk = (const float*)d_in[4];
    const float* wv = (const float*)d_in[5];
    const float* bv = (const float*)d_in[6];
    const float* wo = (const float*)d_in[7];
    const float* bo = (const float*)d_in[8];
    float* out = (float*)d_out;

    static bool attr_done = false;
    if (!attr_done) {
        cudaFuncSetAttribute((hfs_gemm<0,3>),  cudaFuncAttributeMaxDynamicSharedMemorySize, SMEM_NT4);
        cudaFuncSetAttribute((hfs_gemm<0,1>),  cudaFuncAttributeMaxDynamicSharedMemorySize, SMEM_NT1);
        cudaFuncSetAttribute((hfs_gemm<2,23>), cudaFuncAttributeMaxDynamicSharedMemorySize, SMEM_NT4);
        attr_done = true;
    }

    hf *xh,*xl,*wch,*wcl,*woh,*wol;
    hf *qh,*ql,*kh,*kl,*vth,*sh,*yh;
    float *s, *py;
    cudaGetSymbolAddress((void**)&xh, g_xh);   cudaGetSymbolAddress((void**)&xl, g_xl);
    cudaGetSymbolAddress((void**)&wch, g_wch); cudaGetSymbolAddress((void**)&wcl, g_wcl);
    cudaGetSymbolAddress((void**)&woh, g_woh); cudaGetSymbolAddress((void**)&wol, g_wol);
    cudaGetSymbolAddress((void**)&qh, g_qh);   cudaGetSymbolAddress((void**)&ql, g_ql);
    cudaGetSymbolAddress((void**)&kh, g_kh);   cudaGetSymbolAddress((void**)&kl, g_kl);
    cudaGetSymbolAddress((void**)&vth, g_vth);
    cudaGetSymbolAddress((void**)&s, g_s);
    cudaGetSymbolAddress((void**)&sh, g_sh);
    cudaGetSymbolAddress((void**)&yh, g_yh);
    cudaGetSymbolAddress((void**)&py, g_py);

    const dim3 blk(256);

    // 0) all splits in one launch
    {
        dim3 grid(512, 5, 1);
        split_all<<<grid, blk>>>(x, wq, wk, wv, wo, xh, xl, wch, wcl, woh, wol);
    }

    // 1) fused QKV projection (q,k 3-term; v 1-term transposed; heavy-first order)
    {
        dim3 grid(3 * HDIM / 128, MTOT / 128, 1);
        hfs_gemm<2,23><<<grid, blk, SMEM_NT4>>>(
            xh, xl, wch, wcl, bq, bk, bv,
            nullptr, qh, ql, kh, kl, vth, vth,
            MTOT, 3 * HDIM, NDIM, NDIM, NDIM, HDIM, 1, 0, 0, 0, 0, 0, 0);
    }

    // 2) scores = Q K^T (fp32, 3-term)
    {
        dim3 grid(SEQ / 128, SEQ / 128, BATCH);
        hfs_gemm<0,3><<<grid, blk, SMEM_NT4>>>(
            qh, ql, kh, kl, nullptr, nullptr, nullptr,
            s, nullptr, nullptr, nullptr, nullptr, nullptr, nullptr,
            SEQ, SEQ, HDIM, HDIM, HDIM, SEQ, 1,
            (long long)SEQ * HDIM, (long long)SEQ * HDIM, (long long)SEQ * SEQ,
            0, 0, 0);
    }

    // 3) softmax -> fp16 probs
    softmax_h<<<BATCH * SEQ, blk>>>(s, sh);

    // 4) y = P V  (1-term, 3-stage pipeline; split-K=2)
    {
        dim3 grid(HDIM / 128, SEQ / 128, BATCH * 2);
        hfs_gemm<0,1><<<grid, blk, SMEM_NT1>>>(
            sh, sh, vth, vth, nullptr, nullptr, nullptr,
            py, nullptr, nullptr, nullptr, nullptr, nullptr, nullptr,
            SEQ, HDIM, SEQ / 2, SEQ, SEQ, HDIM, 2,
            (long long)SEQ * SEQ, (long long)HDIM * SEQ, (long long)SEQ * HDIM,
            SEQ / 2, SEQ / 2, (long long)MTOT * HDIM);
    }
    combine_h<<<512, blk>>>(py, py + (long long)MTOT * HDIM, yh, MTOT * HDIM / 4);

    // 5) out = Y Wo^T + bo (1-term, 3-stage pipeline, bias folded, direct write)
    {
        dim3 grid(NDIM / 128, MTOT / 128, 1);
        hfs_gemm<0,1><<<grid, blk, SMEM_NT1>>>(
            yh, yh, woh, woh, bo, nullptr, nullptr,
            out, nullptr, nullptr, nullptr, nullptr, nullptr, nullptr,
            MTOT, NDIM, HDIM, HDIM, HDIM, NDIM, 1,
            0, 0, 0, 0, 0, 0);
    }
}